// round 13
// baseline (speedup 1.0000x reference)
#include <cuda_runtime.h>
#include <cuda_bf16.h>
#include <cstdint>

#define NB        4096
#define NIN       41024
#define NF4       10256            // float4 per perspective row
#define TOTF4     20512            // fused (w then b)
#define NLINES    641              // 512B lines per fused row (20512/32)
#define ULINES    8                // lines per work unit (4KB)
#define UPR       81               // units per row = ceil(641/8)
#define TOTUNITS  (NB * UPR)       // 331776
#define NCTR      32
#define CTRRANGE  (TOTUNITS / NCTR)  // 10368 (exact)
#define CAP       192
#define NL1       128
#define NL2       32
#define NT        256
#define NBLK      740              // 148 SMs * 5 resident blocks

// Global scratch (static __device__ arrays; no runtime allocation).
__device__ int   g_tick[NCTR];
__device__ int   g_rowleft[NB];
__device__ int   g_cnt[2 * NB];
__device__ int   g_idx[2 * NB][CAP];
__device__ float g_val[2 * NB][CAP];

__global__ void init_kernel() {
    const int i = blockIdx.x * blockDim.x + threadIdx.x;
    const int n = gridDim.x * blockDim.x;
    if (i < NCTR) g_tick[i] = i * CTRRANGE;
    for (int r = i; r < NB; r += n)     g_rowleft[r] = UPR;
    for (int v = i; v < 2 * NB; v += n) g_cnt[v] = 0;
}

__device__ __forceinline__ float clip01(float x) {
    return fminf(fmaxf(x, 0.f), 1.f);
}

// Row MLP, run by the warp that retires the row's last scan unit.
// noinline: keep its registers/code out of the hot scan loop.
__device__ __noinline__ void do_mlp(
    int row, int lane, float* s_l0w,
    const float* __restrict__ us,   const float* __restrict__ them,
    const float* __restrict__ W_ft, const float* __restrict__ b_ft,
    const float* __restrict__ W1,   const float* __restrict__ b1,
    const float* __restrict__ W2,   const float* __restrict__ b2,
    const float* __restrict__ Wo,   const float* __restrict__ bo,
    float* __restrict__ out)
{
    __threadfence();   // acquire: pair with writers' release (fence+atomicSub)

    const int c0 = min(g_cnt[2 * row],     CAP);
    const int c1 = min(g_cnt[2 * row + 1], CAP);

    // lane owns output dims lane, lane+32, lane+64, lane+96
    float aw0 = __ldg(&b_ft[lane]);      float ab0 = aw0;
    float aw1 = __ldg(&b_ft[lane + 32]); float ab1 = aw1;
    float aw2 = __ldg(&b_ft[lane + 64]); float ab2 = aw2;
    float aw3 = __ldg(&b_ft[lane + 96]); float ab3 = aw3;

    #pragma unroll 4
    for (int f = 0; f < c0; ++f) {
        const float val = g_val[2 * row][f];
        const float* wr = W_ft + g_idx[2 * row][f] * NL1 + lane;
        aw0 += val * __ldg(wr);
        aw1 += val * __ldg(wr + 32);
        aw2 += val * __ldg(wr + 64);
        aw3 += val * __ldg(wr + 96);
    }
    #pragma unroll 4
    for (int f = 0; f < c1; ++f) {
        const float val = g_val[2 * row + 1][f];
        const float* wr = W_ft + g_idx[2 * row + 1][f] * NL1 + lane;
        ab0 += val * __ldg(wr);
        ab1 += val * __ldg(wr + 32);
        ab2 += val * __ldg(wr + 64);
        ab3 += val * __ldg(wr + 96);
    }

    const float uu = __ldg(&us[row]);
    const float tt = __ldg(&them[row]);
    s_l0w[lane]             = clip01(uu * aw0 + tt * ab0);
    s_l0w[lane + 32]        = clip01(uu * aw1 + tt * ab1);
    s_l0w[lane + 64]        = clip01(uu * aw2 + tt * ab2);
    s_l0w[lane + 96]        = clip01(uu * aw3 + tt * ab3);
    s_l0w[NL1 + lane]       = clip01(uu * ab0 + tt * aw0);
    s_l0w[NL1 + lane + 32]  = clip01(uu * ab1 + tt * aw1);
    s_l0w[NL1 + lane + 64]  = clip01(uu * ab2 + tt * aw2);
    s_l0w[NL1 + lane + 96]  = clip01(uu * ab3 + tt * aw3);
    __syncwarp();

    float a1 = __ldg(&b1[lane]);
    #pragma unroll 8
    for (int i = 0; i < 2 * NL1; ++i)
        a1 += s_l0w[i] * __ldg(&W1[i * NL2 + lane]);
    const float l1v = clip01(a1);
    __syncwarp();

    float a2 = __ldg(&b2[lane]);
    #pragma unroll
    for (int i = 0; i < NL2; ++i) {
        const float li = __shfl_sync(0xffffffffu, l1v, i);
        a2 += li * __ldg(&W2[i * NL2 + lane]);
    }
    const float l2v = clip01(a2);

    float r = l2v * __ldg(&Wo[lane]);
    #pragma unroll
    for (int off = 16; off > 0; off >>= 1)
        r += __shfl_down_sync(0xffffffffu, r, off);
    if (lane == 0) out[row] = r + __ldg(&bo[0]);
}

// Dynamic all-warps-scan kernel: every warp claims 4KB scan units from 32
// banded ticket counters (work-stealing kills ragged tails), compacts sparse
// features into L2-resident global lists, and the warp retiring a row's last
// unit runs that row's MLP inline. Claims/tickets hide in LDG shadows.
__global__ void __launch_bounds__(NT, 5) nnue_dyn_kernel(
    const float* __restrict__ us,   const float* __restrict__ them,
    const float* __restrict__ w_in, const float* __restrict__ b_in,
    const float* __restrict__ W_ft, const float* __restrict__ b_ft,
    const float* __restrict__ W1,   const float* __restrict__ b1,
    const float* __restrict__ W2,   const float* __restrict__ b2,
    const float* __restrict__ Wo,   const float* __restrict__ bo,
    float* __restrict__ out)
{
    __shared__ float s_l0[8][2 * NL1];    // per-warp MLP buffer

    const int lane = threadIdx.x & 31;
    const int wid  = threadIdx.x >> 5;
    const int gwid = blockIdx.x * 8 + wid;
    float* s_l0w = &s_l0[wid][0];

    int ctr = gwid & (NCTR - 1);
    const int step = (((gwid >> 5) << 1) | 1) & (NCTR - 1);   // odd stride
    unsigned exhausted = 0u;
    int pendRow = -1;

    while (true) {
        // ---- claim a unit (lane 0 atomic, broadcast) ----
        int u = 0;
        if (lane == 0) u = atomicAdd(&g_tick[ctr], 1);
        u = __shfl_sync(0xffffffffu, u, 0);

        if (u >= (ctr + 1) * CTRRANGE) {
            exhausted |= 1u << ctr;
            if (exhausted == 0xffffffffu) break;
            do { ctr = (ctr + step) & (NCTR - 1); } while ((exhausted >> ctr) & 1u);
            continue;
        }

        const int row = u / UPR;
        const int cu  = u - row * UPR;
        const int l0  = cu * ULINES;

        const float4* __restrict__ w4 = (const float4*)(w_in + (size_t)row * NIN);
        const float4* __restrict__ b4 = (const float4*)(b_in + (size_t)row * NIN);

        // ---- issue the 8-deep load batch (in flight during bookkeeping) ----
        float4 v[ULINES];
        #pragma unroll
        for (int k = 0; k < ULINES; ++k) {
            const int line = l0 + k;
            if (line < NLINES) {
                const int i = line * 32 + lane;
                v[k] = __ldcs((i < NF4) ? (w4 + i) : (b4 + (i - NF4)));
            } else {
                v[k] = make_float4(0.f, 0.f, 0.f, 0.f);
            }
        }

        // ---- deferred completion ticket for the previous unit (in shadow) ----
        int old = 0;
        if (pendRow >= 0) {
            __threadfence();      // release: prior list writes before the sub
            if (lane == 0) old = atomicSub(&g_rowleft[pendRow], 1);
            old = __shfl_sync(0xffffffffu, old, 0);
        }

        // ---- drain: compact nonzeros into this row's global lists ----
        #pragma unroll
        for (int k = 0; k < ULINES; ++k) {
            const int ix = __float_as_int(v[k].x);
            const int iy = __float_as_int(v[k].y);
            const int iz = __float_as_int(v[k].z);
            const int iw = __float_as_int(v[k].w);
            if ((ix | iy | iz | iw) != 0) {        // values are {0.0f, 1.0f}
                const int i   = (l0 + k) * 32 + lane;
                const int p   = (i >= NF4);
                const int vr  = row * 2 + p;
                const int col = (i - p * NF4) * 4;
                if (ix) { int q = atomicAdd(&g_cnt[vr], 1); if (q < CAP) { g_idx[vr][q] = col + 0; g_val[vr][q] = v[k].x; } }
                if (iy) { int q = atomicAdd(&g_cnt[vr], 1); if (q < CAP) { g_idx[vr][q] = col + 1; g_val[vr][q] = v[k].y; } }
                if (iz) { int q = atomicAdd(&g_cnt[vr], 1); if (q < CAP) { g_idx[vr][q] = col + 2; g_val[vr][q] = v[k].z; } }
                if (iw) { int q = atomicAdd(&g_cnt[vr], 1); if (q < CAP) { g_idx[vr][q] = col + 3; g_val[vr][q] = v[k].w; } }
            }
        }

        // ---- if we retired the previous row's last unit: run its MLP ----
        if (old == 1)
            do_mlp(pendRow, lane, s_l0w, us, them, W_ft, b_ft,
                   W1, b1, W2, b2, Wo, bo, out);

        pendRow = row;
    }

    // flush the final pending ticket
    if (pendRow >= 0) {
        __threadfence();
        int old = 0;
        if (lane == 0) old = atomicSub(&g_rowleft[pendRow], 1);
        old = __shfl_sync(0xffffffffu, old, 0);
        if (old == 1)
            do_mlp(pendRow, lane, s_l0w, us, them, W_ft, b_ft,
                   W1, b1, W2, b2, Wo, bo, out);
    }
}

extern "C" void kernel_launch(void* const* d_in, const int* in_sizes, int n_in,
                              void* d_out, int out_size) {
    const float* us   = (const float*)d_in[0];
    const float* them = (const float*)d_in[1];
    const float* w_in = (const float*)d_in[2];
    const float* b_in = (const float*)d_in[3];
    const float* W_ft = (const float*)d_in[4];
    const float* b_ft = (const float*)d_in[5];
    const float* W1   = (const float*)d_in[6];
    const float* b1   = (const float*)d_in[7];
    const float* W2   = (const float*)d_in[8];
    const float* b2   = (const float*)d_in[9];
    const float* Wo   = (const float*)d_in[10];
    const float* bo   = (const float*)d_in[11];
    float* out = (float*)d_out;

    init_kernel<<<64, 256>>>();
    nnue_dyn_kernel<<<NBLK, NT>>>(us, them, w_in, b_in, W_ft, b_ft,
                                  W1, b1, W2, b2, Wo, bo, out);
}

// round 14
// speedup vs baseline: 2.6962x; 2.6962x over previous
#include <cuda_runtime.h>
#include <cuda_bf16.h>
#include <cstdint>

#define NB       4096
#define NINPUTS  41024
#define N4       (NINPUTS / 4)     // 10256 float4 per perspective row
#define TOT4     (2 * N4)          // 20512 combined (w then b)
#define NL1      128
#define NL2      32
#define CAPS     192
#define NT       448               // 13 producer warps + 1 consumer warp
#define NPROD    416
#define U        8                 // float4 loads in flight per producer thread
#define NBLK     444               // 148 SMs * 3 resident blocks

__device__ int g_row;              // next unclaimed row (init = NBLK)

__global__ void init_kernel() {
    if (threadIdx.x == 0) g_row = NBLK;
}

__device__ __forceinline__ float clip01(float x) {
    return fminf(fmaxf(x, 0.f), 1.f);
}

// Warp-specialized persistent kernel, 39 scan-warps/SM + dynamic rows:
// warps 0-12 stream-scan both perspective rows of the current row into a
// double-buffered SMEM compaction list; warp 13 (consumer) claims the NEXT
// row (one global atomic per ~60k-cyc row, fully hidden in its slack) and
// gathers L2-resident W_ft + runs the clipped MLP for the previous row.
// One __syncthreads per row. Hot loop has ZERO global atomics/fences (R13
// lesson). 48-reg budget is load-bearing (R7 lesson): launch_bounds(448,3)
// caps at exactly 48.
__global__ void __launch_bounds__(NT, 3) nnue_ws_kernel(
    const float* __restrict__ us,   const float* __restrict__ them,
    const float* __restrict__ w_in, const float* __restrict__ b_in,
    const float* __restrict__ W_ft, const float* __restrict__ b_ft,
    const float* __restrict__ W1,   const float* __restrict__ b1,
    const float* __restrict__ W2,   const float* __restrict__ b2,
    const float* __restrict__ Wo,   const float* __restrict__ bo,
    float* __restrict__ out)
{
    __shared__ int   s_e[2][CAPS];      // (p<<16) | feature index
    __shared__ float s_v[2][CAPS];
    __shared__ int   s_cnt[2];
    __shared__ int   s_row[2];          // row for iteration k (mod 2)
    __shared__ float s_l0[2 * NL1];     // consumer-private

    const int tid = threadIdx.x;

    if (tid < 2) s_cnt[tid] = 0;
    if (tid == 0) s_row[0] = blockIdx.x;   // first row = static
    __syncthreads();

    if (tid < NPROD) {
        // ================= PRODUCER: pure streaming scan =================
        for (int k = 0; ; ++k) {
            const int row = s_row[k & 1];
            if (row >= NB) break;
            const int kb = k & 1;

            const float4* __restrict__ w4 = (const float4*)(w_in + (size_t)row * NINPUTS);
            const float4* __restrict__ b4 = (const float4*)(b_in + (size_t)row * NINPUTS);

            #pragma unroll 1
            for (int base = 0; base < TOT4; base += NPROD * U) {
                float4 v[U];
                #pragma unroll
                for (int u = 0; u < U; ++u) {
                    const int i = base + u * NPROD + tid;
                    if (i < TOT4) {
                        const float4* p4 = (i < N4) ? (w4 + i) : (b4 + (i - N4));
                        v[u] = __ldcs(p4);       // evict-first: keep W_ft in L2
                    } else {
                        v[u] = make_float4(0.f, 0.f, 0.f, 0.f);
                    }
                }
                #pragma unroll
                for (int u = 0; u < U; ++u) {
                    // integer zero tests: mask values are {0.0f, 1.0f}
                    const int ix = __float_as_int(v[u].x);
                    const int iy = __float_as_int(v[u].y);
                    const int iz = __float_as_int(v[u].z);
                    const int iw = __float_as_int(v[u].w);
                    if ((ix | iy | iz | iw) != 0) {
                        const int i   = base + u * NPROD + tid;
                        const int p   = (i >= N4);
                        const int col = (i - p * N4) * 4;
                        const int tag = p << 16;
                        if (ix) { int q = atomicAdd(&s_cnt[kb], 1); if (q < CAPS) { s_e[kb][q] = tag | (col + 0); s_v[kb][q] = v[u].x; } }
                        if (iy) { int q = atomicAdd(&s_cnt[kb], 1); if (q < CAPS) { s_e[kb][q] = tag | (col + 1); s_v[kb][q] = v[u].y; } }
                        if (iz) { int q = atomicAdd(&s_cnt[kb], 1); if (q < CAPS) { s_e[kb][q] = tag | (col + 2); s_v[kb][q] = v[u].z; } }
                        if (iw) { int q = atomicAdd(&s_cnt[kb], 1); if (q < CAPS) { s_e[kb][q] = tag | (col + 3); s_v[kb][q] = v[u].w; } }
                    }
                }
            }
            __syncthreads();       // row handoff
        }
    } else {
        // ===== CONSUMER: claim next row, then gather + clipped MLP =======
        const int lane = tid & 31;
        int prevR = -1, prevB = 0;

        for (int k = 0; ; ++k) {
            const int row = s_row[k & 1];
            if (row >= NB) break;

            // claim the row for iteration k+1 (hidden: producers are busy
            // scanning row k for ~60k cyc; ATOMG ~320 cyc)
            if (lane == 0) s_row[(k + 1) & 1] = atomicAdd(&g_row, 1);

            if (prevR >= 0) {
                // ---- gather + MLP for the previous row ----
                const int b = prevB;
                int cnt;
                if (lane == 0) { cnt = s_cnt[b]; s_cnt[b] = 0; }   // latch + reset
                cnt = min(__shfl_sync(0xffffffffu, cnt, 0), CAPS);

                float aw0 = 0.f, aw1 = 0.f, aw2 = 0.f, aw3 = 0.f;
                float ab0 = 0.f, ab1 = 0.f, ab2 = 0.f, ab3 = 0.f;
                #pragma unroll 4
                for (int f = 0; f < cnt; ++f) {
                    const int   e   = s_e[b][f];
                    const float val = s_v[b][f];
                    const float* wr = W_ft + (e & 0xFFFF) * NL1 + lane;
                    const float w0 = __ldg(wr);
                    const float w1 = __ldg(wr + 32);
                    const float w2 = __ldg(wr + 64);
                    const float w3 = __ldg(wr + 96);
                    if (e & (1 << 16)) {
                        ab0 += val * w0; ab1 += val * w1; ab2 += val * w2; ab3 += val * w3;
                    } else {
                        aw0 += val * w0; aw1 += val * w1; aw2 += val * w2; aw3 += val * w3;
                    }
                }
                aw0 += __ldg(&b_ft[lane]);       ab0 += __ldg(&b_ft[lane]);
                aw1 += __ldg(&b_ft[lane + 32]);  ab1 += __ldg(&b_ft[lane + 32]);
                aw2 += __ldg(&b_ft[lane + 64]);  ab2 += __ldg(&b_ft[lane + 64]);
                aw3 += __ldg(&b_ft[lane + 96]);  ab3 += __ldg(&b_ft[lane + 96]);

                const float uu = __ldg(&us[prevR]);
                const float tt = __ldg(&them[prevR]);
                s_l0[lane]             = clip01(uu * aw0 + tt * ab0);
                s_l0[lane + 32]        = clip01(uu * aw1 + tt * ab1);
                s_l0[lane + 64]        = clip01(uu * aw2 + tt * ab2);
                s_l0[lane + 96]        = clip01(uu * aw3 + tt * ab3);
                s_l0[NL1 + lane]       = clip01(uu * ab0 + tt * aw0);
                s_l0[NL1 + lane + 32]  = clip01(uu * ab1 + tt * aw1);
                s_l0[NL1 + lane + 64]  = clip01(uu * ab2 + tt * aw2);
                s_l0[NL1 + lane + 96]  = clip01(uu * ab3 + tt * aw3);
                __syncwarp();

                float a1 = __ldg(&b1[lane]);
                #pragma unroll 8
                for (int i = 0; i < 2 * NL1; ++i)
                    a1 += s_l0[i] * __ldg(&W1[i * NL2 + lane]);
                const float l1v = clip01(a1);
                __syncwarp();

                float a2 = __ldg(&b2[lane]);
                #pragma unroll
                for (int i = 0; i < NL2; ++i) {
                    const float li = __shfl_sync(0xffffffffu, l1v, i);
                    a2 += li * __ldg(&W2[i * NL2 + lane]);
                }
                const float l2v = clip01(a2);

                float r = l2v * __ldg(&Wo[lane]);
                #pragma unroll
                for (int off = 16; off > 0; off >>= 1)
                    r += __shfl_down_sync(0xffffffffu, r, off);
                if (lane == 0) out[prevR] = r + __ldg(&bo[0]);
            }

            prevR = row;
            prevB = k & 1;
            __syncthreads();       // row handoff
        }

        // ---- final pending row ----
        if (prevR >= 0) {
            const int b = prevB;
            int cnt;
            if (lane == 0) cnt = s_cnt[b];
            cnt = min(__shfl_sync(0xffffffffu, cnt, 0), CAPS);

            float aw0 = 0.f, aw1 = 0.f, aw2 = 0.f, aw3 = 0.f;
            float ab0 = 0.f, ab1 = 0.f, ab2 = 0.f, ab3 = 0.f;
            #pragma unroll 4
            for (int f = 0; f < cnt; ++f) {
                const int   e   = s_e[b][f];
                const float val = s_v[b][f];
                const float* wr = W_ft + (e & 0xFFFF) * NL1 + lane;
                const float w0 = __ldg(wr);
                const float w1 = __ldg(wr + 32);
                const float w2 = __ldg(wr + 64);
                const float w3 = __ldg(wr + 96);
                if (e & (1 << 16)) {
                    ab0 += val * w0; ab1 += val * w1; ab2 += val * w2; ab3 += val * w3;
                } else {
                    aw0 += val * w0; aw1 += val * w1; aw2 += val * w2; aw3 += val * w3;
                }
            }
            aw0 += __ldg(&b_ft[lane]);       ab0 += __ldg(&b_ft[lane]);
            aw1 += __ldg(&b_ft[lane + 32]);  ab1 += __ldg(&b_ft[lane + 32]);
            aw2 += __ldg(&b_ft[lane + 64]);  ab2 += __ldg(&b_ft[lane + 64]);
            aw3 += __ldg(&b_ft[lane + 96]);  ab3 += __ldg(&b_ft[lane + 96]);

            const float uu = __ldg(&us[prevR]);
            const float tt = __ldg(&them[prevR]);
            s_l0[lane]             = clip01(uu * aw0 + tt * ab0);
            s_l0[lane + 32]        = clip01(uu * aw1 + tt * ab1);
            s_l0[lane + 64]        = clip01(uu * aw2 + tt * ab2);
            s_l0[lane + 96]        = clip01(uu * aw3 + tt * ab3);
            s_l0[NL1 + lane]       = clip01(uu * ab0 + tt * aw0);
            s_l0[NL1 + lane + 32]  = clip01(uu * ab1 + tt * aw1);
            s_l0[NL1 + lane + 64]  = clip01(uu * ab2 + tt * aw2);
            s_l0[NL1 + lane + 96]  = clip01(uu * ab3 + tt * aw3);
            __syncwarp();

            float a1 = __ldg(&b1[lane]);
            #pragma unroll 8
            for (int i = 0; i < 2 * NL1; ++i)
                a1 += s_l0[i] * __ldg(&W1[i * NL2 + lane]);
            const float l1v = clip01(a1);
            __syncwarp();

            float a2 = __ldg(&b2[lane]);
            #pragma unroll
            for (int i = 0; i < NL2; ++i) {
                const float li = __shfl_sync(0xffffffffu, l1v, i);
                a2 += li * __ldg(&W2[i * NL2 + lane]);
            }
            const float l2v = clip01(a2);

            float r = l2v * __ldg(&Wo[lane]);
            #pragma unroll
            for (int off = 16; off > 0; off >>= 1)
                r += __shfl_down_sync(0xffffffffu, r, off);
            if (lane == 0) out[prevR] = r + __ldg(&bo[0]);
        }
    }
}

extern "C" void kernel_launch(void* const* d_in, const int* in_sizes, int n_in,
                              void* d_out, int out_size) {
    const float* us   = (const float*)d_in[0];
    const float* them = (const float*)d_in[1];
    const float* w_in = (const float*)d_in[2];
    const float* b_in = (const float*)d_in[3];
    const float* W_ft = (const float*)d_in[4];
    const float* b_ft = (const float*)d_in[5];
    const float* W1   = (const float*)d_in[6];
    const float* b1   = (const float*)d_in[7];
    const float* W2   = (const float*)d_in[8];
    const float* b2   = (const float*)d_in[9];
    const float* Wo   = (const float*)d_in[10];
    const float* bo   = (const float*)d_in[11];
    float* out = (float*)d_out;

    init_kernel<<<1, 32>>>();
    nnue_ws_kernel<<<NBLK, NT>>>(us, them, w_in, b_in, W_ft, b_ft,
                                 W1, b1, W2, b2, Wo, bo, out);
}

// round 15
// speedup vs baseline: 3.4630x; 1.2844x over previous
#include <cuda_runtime.h>
#include <cuda_bf16.h>
#include <cstdint>

#define NB       4096
#define NIN      41024
#define NF4      10256             // float4 per perspective row
#define STG_F4   641               // float4 per stage (16 stages per perspective)
#define STGB     (STG_F4 * 16)     // 10256 bytes per stage
#define NSTGROW  32                // stages per fused row (16 w + 16 b)
#define NRING    3
#define NL1      128
#define NL2      32
#define CAPS     192
#define NT       256               // warps 0-6 scan (224 thr), warp 7 = consumer
#define NSCAN    224
#define NBLK     888               // 148 SMs * 6 resident blocks

__device__ __forceinline__ float clip01(float x) {
    return fminf(fmaxf(x, 0.f), 1.f);
}

__device__ __forceinline__ unsigned smem_u32(const void* p) {
    return (unsigned)__cvta_generic_to_shared(p);
}
__device__ __forceinline__ void mbar_init(unsigned a, unsigned cnt) {
    asm volatile("mbarrier.init.shared.b64 [%0], %1;" :: "r"(a), "r"(cnt) : "memory");
}
__device__ __forceinline__ void mbar_expect_tx(unsigned a, unsigned bytes) {
    asm volatile("mbarrier.arrive.expect_tx.shared.b64 _, [%0], %1;"
                 :: "r"(a), "r"(bytes) : "memory");
}
__device__ __forceinline__ void mbar_arrive(unsigned a) {
    asm volatile("mbarrier.arrive.shared.b64 _, [%0];" :: "r"(a) : "memory");
}
__device__ __forceinline__ void mbar_wait(unsigned a, unsigned phase) {
    asm volatile(
        "{\n\t.reg .pred P;\n\t"
        "W_%=:\n\t"
        "mbarrier.try_wait.parity.acquire.cta.shared::cta.b64 P, [%0], %1, 0x989680;\n\t"
        "@P bra.uni D_%=;\n\t"
        "bra.uni W_%=;\n\t"
        "D_%=:\n\t}"
        :: "r"(a), "r"(phase) : "memory");
}
__device__ __forceinline__ void tma_1d(unsigned dst, const void* src,
                                       unsigned bytes, unsigned mbar,
                                       unsigned long long pol) {
    asm volatile(
        "cp.async.bulk.shared::cluster.global.mbarrier::complete_tx::bytes.L2::cache_hint"
        " [%0], [%1], %2, [%3], %4;"
        :: "r"(dst), "l"(src), "r"(bytes), "r"(mbar), "l"(pol) : "memory");
}

// TMA-fed warp-specialized kernel: one thread issues 10KB bulk copies into a
// 3-slot SMEM ring (fetch decoupled from scan; no register batching -> the
// 51-reg wall from R7/R14 is gone and 6 blocks/SM fit); warps 0-6 scan the
// resident stage from SMEM and compact nonzeros into double-buffered lists;
// warp 7 (R6-proven consumer) gathers L2-resident W_ft + runs the clipped
// MLP for the previous row. One __syncthreads per row; the hot loop has zero
// global atomics/fences (R13 lesson).
__global__ void __launch_bounds__(NT, 6) nnue_tma_kernel(
    const float* __restrict__ us,   const float* __restrict__ them,
    const float* __restrict__ w_in, const float* __restrict__ b_in,
    const float* __restrict__ W_ft, const float* __restrict__ b_ft,
    const float* __restrict__ W1,   const float* __restrict__ b1,
    const float* __restrict__ W2,   const float* __restrict__ b2,
    const float* __restrict__ Wo,   const float* __restrict__ bo,
    float* __restrict__ out)
{
    __shared__ __align__(128) char s_stg[NRING][STGB];
    __shared__ __align__(8) unsigned long long s_full[NRING];
    __shared__ __align__(8) unsigned long long s_empty[NRING];
    __shared__ int   s_e[2][CAPS];      // (p<<16) | feature index
    __shared__ float s_v[2][CAPS];
    __shared__ int   s_cnt[2];
    __shared__ float s_l0[2 * NL1];     // consumer-private

    const int tid = threadIdx.x;
    const unsigned fullb  = smem_u32(&s_full[0]);
    const unsigned emptyb = smem_u32(&s_empty[0]);
    const unsigned stgb   = smem_u32(&s_stg[0][0]);

    if (tid == 0) {
        #pragma unroll
        for (int s = 0; s < NRING; ++s) {
            mbar_init(fullb + s * 8, 1);        // expect_tx arrival
            mbar_init(emptyb + s * 8, NSCAN);   // all scan threads
        }
    }
    if (tid < 2) s_cnt[tid] = 0;
    __syncthreads();

    if (tid < NSCAN) {
        // ============ SCAN WARPS (0-6); thread 0 also issues TMA ============
        unsigned long long pol = 0;
        if (tid == 0)
            asm("createpolicy.fractional.L2::evict_first.b64 %0, 1.0;" : "=l"(pol));

        // issue stage #ip of this block's stage stream (32 per row)
        auto issue = [&](int ip) {
            const int rowi = ip >> 5;
            const int row  = blockIdx.x + rowi * gridDim.x;
            if (row >= NB) return;
            const int s    = ip & 31;
            const int slot = ip % NRING;
            if (ip >= NRING)
                mbar_wait(emptyb + slot * 8, ((ip / NRING) + 1) & 1);
            const float* src = (s < 16)
                ? (w_in + (size_t)row * NIN + (size_t)s * (STG_F4 * 4))
                : (b_in + (size_t)row * NIN + (size_t)(s - 16) * (STG_F4 * 4));
            mbar_expect_tx(fullb + slot * 8, STGB);
            tma_1d(stgb + slot * STGB, src, STGB, fullb + slot * 8, pol);
        };

        if (tid == 0) { issue(0); issue(1); issue(2); }

        int k = 0, i = 0;
        for (int row = blockIdx.x; row < NB; row += gridDim.x, ++i) {
            const int kb = i & 1;
            #pragma unroll 1
            for (int s = 0; s < NSTGROW; ++s, ++k) {
                const int slot = k % NRING;
                mbar_wait(fullb + slot * 8, (k / NRING) & 1);

                const float4* stg4 = (const float4*)(&s_stg[slot][0]);
                const int p    = s >> 4;
                const int rel0 = (s & 15) * STG_F4;
                const int tag  = p << 16;
                #pragma unroll 1
                for (int j = tid; j < STG_F4; j += NSCAN) {
                    const float4 vv = stg4[j];
                    // integer zero tests: mask values are {0.0f, 1.0f}
                    const int ix = __float_as_int(vv.x);
                    const int iy = __float_as_int(vv.y);
                    const int iz = __float_as_int(vv.z);
                    const int iw = __float_as_int(vv.w);
                    if ((ix | iy | iz | iw) != 0) {
                        const int col = (rel0 + j) * 4;
                        if (ix) { int q = atomicAdd(&s_cnt[kb], 1); if (q < CAPS) { s_e[kb][q] = tag | (col + 0); s_v[kb][q] = vv.x; } }
                        if (iy) { int q = atomicAdd(&s_cnt[kb], 1); if (q < CAPS) { s_e[kb][q] = tag | (col + 1); s_v[kb][q] = vv.y; } }
                        if (iz) { int q = atomicAdd(&s_cnt[kb], 1); if (q < CAPS) { s_e[kb][q] = tag | (col + 2); s_v[kb][q] = vv.z; } }
                        if (iw) { int q = atomicAdd(&s_cnt[kb], 1); if (q < CAPS) { s_e[kb][q] = tag | (col + 3); s_v[kb][q] = vv.w; } }
                    }
                }

                mbar_arrive(emptyb + slot * 8);
                if (tid == 0) issue(k + NRING);
            }
            __syncthreads();       // row handoff to consumer
        }
    } else {
        // ================= CONSUMER (warp 7): gather + MLP ================
        const int lane = tid & 31;
        int i = 0;
        for (int row = blockIdx.x; row < NB; row += gridDim.x, ++i) {
            __syncthreads();       // wait for scan warps to finish this row
            const int kb = i & 1;

            int cnt;
            if (lane == 0) { cnt = s_cnt[kb]; s_cnt[kb] = 0; }   // latch + reset
            cnt = min(__shfl_sync(0xffffffffu, cnt, 0), CAPS);

            // Gather: lane owns dims lane, lane+32, lane+64, lane+96.
            float aw0 = 0.f, aw1 = 0.f, aw2 = 0.f, aw3 = 0.f;
            float ab0 = 0.f, ab1 = 0.f, ab2 = 0.f, ab3 = 0.f;
            #pragma unroll 4
            for (int f = 0; f < cnt; ++f) {
                const int   e   = s_e[kb][f];
                const float val = s_v[kb][f];
                const float* wr = W_ft + (e & 0xFFFF) * NL1 + lane;
                const float w0 = __ldg(wr);
                const float w1 = __ldg(wr + 32);
                const float w2 = __ldg(wr + 64);
                const float w3 = __ldg(wr + 96);
                if (e & (1 << 16)) {
                    ab0 += val * w0; ab1 += val * w1; ab2 += val * w2; ab3 += val * w3;
                } else {
                    aw0 += val * w0; aw1 += val * w1; aw2 += val * w2; aw3 += val * w3;
                }
            }
            aw0 += __ldg(&b_ft[lane]);       ab0 += __ldg(&b_ft[lane]);
            aw1 += __ldg(&b_ft[lane + 32]);  ab1 += __ldg(&b_ft[lane + 32]);
            aw2 += __ldg(&b_ft[lane + 64]);  ab2 += __ldg(&b_ft[lane + 64]);
            aw3 += __ldg(&b_ft[lane + 96]);  ab3 += __ldg(&b_ft[lane + 96]);

            const float uu = __ldg(&us[row]);
            const float tt = __ldg(&them[row]);
            s_l0[lane]             = clip01(uu * aw0 + tt * ab0);
            s_l0[lane + 32]        = clip01(uu * aw1 + tt * ab1);
            s_l0[lane + 64]        = clip01(uu * aw2 + tt * ab2);
            s_l0[lane + 96]        = clip01(uu * aw3 + tt * ab3);
            s_l0[NL1 + lane]       = clip01(uu * ab0 + tt * aw0);
            s_l0[NL1 + lane + 32]  = clip01(uu * ab1 + tt * aw1);
            s_l0[NL1 + lane + 64]  = clip01(uu * ab2 + tt * aw2);
            s_l0[NL1 + lane + 96]  = clip01(uu * ab3 + tt * aw3);
            __syncwarp();

            float a1 = __ldg(&b1[lane]);
            #pragma unroll 8
            for (int ii = 0; ii < 2 * NL1; ++ii)
                a1 += s_l0[ii] * __ldg(&W1[ii * NL2 + lane]);
            const float l1v = clip01(a1);
            __syncwarp();

            float a2 = __ldg(&b2[lane]);
            #pragma unroll
            for (int ii = 0; ii < NL2; ++ii) {
                const float li = __shfl_sync(0xffffffffu, l1v, ii);
                a2 += li * __ldg(&W2[ii * NL2 + lane]);
            }
            const float l2v = clip01(a2);

            float r = l2v * __ldg(&Wo[lane]);
            #pragma unroll
            for (int off = 16; off > 0; off >>= 1)
                r += __shfl_down_sync(0xffffffffu, r, off);
            if (lane == 0) out[row] = r + __ldg(&bo[0]);
        }
    }
}

extern "C" void kernel_launch(void* const* d_in, const int* in_sizes, int n_in,
                              void* d_out, int out_size) {
    const float* us   = (const float*)d_in[0];
    const float* them = (const float*)d_in[1];
    const float* w_in = (const float*)d_in[2];
    const float* b_in = (const float*)d_in[3];
    const float* W_ft = (const float*)d_in[4];
    const float* b_ft = (const float*)d_in[5];
    const float* W1   = (const float*)d_in[6];
    const float* b1   = (const float*)d_in[7];
    const float* W2   = (const float*)d_in[8];
    const float* b2   = (const float*)d_in[9];
    const float* Wo   = (const float*)d_in[10];
    const float* bo   = (const float*)d_in[11];
    float* out = (float*)d_out;

    nnue_tma_kernel<<<NBLK, NT>>>(us, them, w_in, b_in, W_ft, b_ft,
                                  W1, b1, W2, b2, Wo, bo, out);
}